// round 1
// baseline (speedup 1.0000x reference)
#include <cuda_runtime.h>
#include <cstdint>
#include <cstdio>

#define B_   256
#define T_   600
#define I_   129
#define H_   200
#define G_   800   // 4*H

// ---------------- scratch (device globals; no cudaMalloc allowed) ----------------
__device__ float g_xg[(size_t)T_ * B_ * G_];    // 491.5 MB (shared by layer1 & layer2)
__device__ float g_h1[(size_t)T_ * B_ * H_];    // 122.9 MB
__device__ float g_h2[(size_t)T_ * B_ * H_];    // 122.9 MB
__device__ float g_tmp[(size_t)T_ * B_ * I_];   // 79.3 MB  (x-transposed, later y1)

__device__ unsigned g_bar_count = 0;
__device__ unsigned g_bar_gen   = 0;

// ---------------- grid barrier (all blocks co-resident) ----------------
__device__ __forceinline__ void grid_barrier()
{
    __syncthreads();
    if (threadIdx.x == 0) {
        __threadfence();
        unsigned gen = atomicAdd(&g_bar_gen, 0u);
        if (atomicAdd(&g_bar_count, 1u) == gridDim.x - 1) {
            atomicExch(&g_bar_count, 0u);
            __threadfence();
            atomicAdd(&g_bar_gen, 1u);
        } else {
            while (atomicAdd(&g_bar_gen, 0u) == gen) { __nanosleep(64); }
        }
        __threadfence();
    }
    __syncthreads();
}

__device__ __forceinline__ float sigm(float x) { return 1.f / (1.f + expf(-x)); }

// ---------------- transpose x [B,I,T] -> xt [(t*B+b), I] ----------------
__global__ void transpose_x(const float* __restrict__ x, float* __restrict__ xt)
{
    __shared__ float sm[32][33];
    const int b  = blockIdx.z;
    const int i0 = blockIdx.y * 32;
    const int t0 = blockIdx.x * 32;
    const int tx = threadIdx.x, ty = threadIdx.y; // block (32,8)
#pragma unroll
    for (int s = 0; s < 32; s += 8) {
        int i = i0 + ty + s, t = t0 + tx;
        sm[ty + s][tx] = (i < I_ && t < T_) ? x[((size_t)b * I_ + i) * T_ + t] : 0.f;
    }
    __syncthreads();
#pragma unroll
    for (int s = 0; s < 32; s += 8) {
        int t = t0 + ty + s, i = i0 + tx;
        if (t < T_ && i < I_)
            xt[((size_t)t * B_ + b) * I_ + i] = sm[tx][ty + s];
    }
}

// ---------------- generic row-major GEMM: out = A[M,K] * W[N,K]^T (+bias, act) ----
// MODE 0: out[row*N+n] = v + bias[n] + bias2[n]
// MODE 1: out[row*N+n] = relu(v + bias[n])
// MODE 2: out[(b*129+n)*600+t] = sigmoid(v + bias[n]),  t=row>>8, b=row&255
template <int MODE>
__global__ void __launch_bounds__(256) gemm_rm(
    const float* __restrict__ A, const float* __restrict__ W,
    const float* __restrict__ bias, const float* __restrict__ bias2,
    float* __restrict__ out, int M, int K, int N)
{
    __shared__ __align__(16) float A_sm[32 * 68];
    __shared__ __align__(16) float W_sm[32 * 68];
    const int tid  = threadIdx.x;
    const int row0 = blockIdx.y * 64;
    const int n0   = blockIdx.x * 64;
    const int tc   = tid & 15, tr = tid >> 4;

    float acc[4][4] = {};

    for (int k0 = 0; k0 < K; k0 += 32) {
        for (int idx = tid; idx < 2048; idx += 256) {
            int r  = idx >> 5, kk = idx & 31;
            int k  = k0 + kk;
            int row = row0 + r, n = n0 + r;
            float va = 0.f, vw = 0.f;
            if (k < K && row < M) va = A[(size_t)row * K + k];
            if (k < K && n   < N) vw = W[(size_t)n   * K + k];
            A_sm[kk * 68 + r] = va;
            W_sm[kk * 68 + r] = vw;
        }
        __syncthreads();
#pragma unroll
        for (int kk = 0; kk < 32; ++kk) {
            float4 a = *(const float4*)(A_sm + kk * 68 + tr * 4);
            float4 w = *(const float4*)(W_sm + kk * 68 + tc * 4);
            acc[0][0] += a.x * w.x; acc[0][1] += a.x * w.y; acc[0][2] += a.x * w.z; acc[0][3] += a.x * w.w;
            acc[1][0] += a.y * w.x; acc[1][1] += a.y * w.y; acc[1][2] += a.y * w.z; acc[1][3] += a.y * w.w;
            acc[2][0] += a.z * w.x; acc[2][1] += a.z * w.y; acc[2][2] += a.z * w.z; acc[2][3] += a.z * w.w;
            acc[3][0] += a.w * w.x; acc[3][1] += a.w * w.y; acc[3][2] += a.w * w.z; acc[3][3] += a.w * w.w;
        }
        __syncthreads();
    }

#pragma unroll
    for (int i = 0; i < 4; ++i) {
        int row = row0 + tr * 4 + i;
        if (row >= M) continue;
#pragma unroll
        for (int j = 0; j < 4; ++j) {
            int n = n0 + tc * 4 + j;
            if (n >= N) continue;
            float v = acc[i][j] + bias[n];
            if (MODE == 0) {
                v += bias2[n];
                out[(size_t)row * N + n] = v;
            } else if (MODE == 1) {
                out[(size_t)row * N + n] = fmaxf(v, 0.f);
            } else {
                int t = row >> 8, b = row & 255;
                out[((size_t)b * I_ + n) * T_ + t] = sigm(v);
            }
        }
    }
}

// ---------------- persistent LSTM scan -----------------------------------------
// grid = 100 blocks (4 batch-tiles of 64  x  25 unit-tiles of 8), 256 threads.
// Each thread owns (2 batches) x (1 unit) x (4 gates); cell state in registers.
// w_hh slice lives in smem for the whole scan (u-stride 820 -> conflict-free LDS.128).
// h tile in smem, [b][k] with stride 204 (conflict-free).
__global__ void __launch_bounds__(256, 1) lstm_scan(
    const float* __restrict__ xg, const float* __restrict__ whh,
    float* __restrict__ hout)
{
    extern __shared__ float sm[];
    float* h_sm = sm;               // 64 * 204 = 13056 floats
    float* w_sm = sm + 64 * 204;    // 8 * 820  = 6560  floats

    const int tid  = threadIdx.x;
    const int bb   = blockIdx.x & 3;
    const int uu   = blockIdx.x >> 2;
    const int b0   = bb * 64;
    const int u_l  = tid & 7;
    const int bgrp = tid >> 3;
    const int u    = uu * 8 + u_l;
    const int b_idx0 = b0 + bgrp * 2;

    // load w_hh slice once: w_sm[u'][k][gate], u-stride 820 (bank-conflict-free)
    for (int idx = tid; idx < 8 * 200 * 4; idx += 256) {
        int g   = idx / 1600;
        int rem = idx - g * 1600;
        int up  = rem / 200;
        int k   = rem - up * 200;
        w_sm[up * 820 + k * 4 + g] = whh[((size_t)(g * H_ + uu * 8 + up)) * H_ + k];
    }

    float c0 = 0.f, c1 = 0.f;

    for (int t = 0; t < T_; ++t) {
        // stage previous h into smem
        if (t == 0) {
            for (int idx = tid; idx < 64 * 204; idx += 256) h_sm[idx] = 0.f;
        } else {
            const float* hp = hout + (size_t)(t - 1) * B_ * H_;
            for (int idx = tid; idx < 64 * 50; idx += 256) {
                int bi = idx / 50;
                int k4 = idx - bi * 50;
                float4 v = *(const float4*)(hp + (size_t)(b0 + bi) * H_ + k4 * 4);
                *(float4*)(h_sm + bi * 204 + k4 * 4) = v;
            }
        }
        __syncthreads();

        // prefetch the precomputed input-gate contributions (includes both biases)
        const float* xr = xg + ((size_t)t * B_ + b_idx0) * G_ + u;
        float xa00 = xr[0],   xa01 = xr[H_],      xa02 = xr[2 * H_],      xa03 = xr[3 * H_];
        float xa10 = xr[G_],  xa11 = xr[G_ + H_], xa12 = xr[G_ + 2 * H_], xa13 = xr[G_ + 3 * H_];

        // recurrent GEMM: 2 batches x 4 gates, K = 200
        float a00 = 0, a01 = 0, a02 = 0, a03 = 0;
        float a10 = 0, a11 = 0, a12 = 0, a13 = 0;
        const float*  hr0 = h_sm + (bgrp * 2) * 204;
        const float*  hr1 = hr0 + 204;
        const float4* wr  = (const float4*)(w_sm + u_l * 820);
#pragma unroll 8
        for (int k = 0; k < H_; ++k) {
            float4 w4 = wr[k];
            float h0 = hr0[k], h1 = hr1[k];
            a00 += h0 * w4.x; a01 += h0 * w4.y; a02 += h0 * w4.z; a03 += h0 * w4.w;
            a10 += h1 * w4.x; a11 += h1 * w4.y; a12 += h1 * w4.z; a13 += h1 * w4.w;
        }

        // gates + cell update (c stays in registers across all 600 steps)
        float ig = sigm(a00 + xa00);
        float fg = sigm(a01 + xa01);
        float gg = tanhf(a02 + xa02);
        float og = sigm(a03 + xa03);
        c0 = fg * c0 + ig * gg;
        float h0o = og * tanhf(c0);

        ig = sigm(a10 + xa10);
        fg = sigm(a11 + xa11);
        gg = tanhf(a12 + xa12);
        og = sigm(a13 + xa13);
        c1 = fg * c1 + ig * gg;
        float h1o = og * tanhf(c1);

        float* ho = hout + ((size_t)t * B_ + b_idx0) * H_ + u;
        ho[0]  = h0o;
        ho[H_] = h1o;

        __threadfence();
        grid_barrier();
    }
}

// ---------------- launch --------------------------------------------------------
extern "C" void kernel_launch(void* const* d_in, const int* in_sizes, int n_in,
                              void* d_out, int out_size)
{
    const float* x     = (const float*)d_in[0];
    const float* w_ih1 = (const float*)d_in[1];
    const float* w_hh1 = (const float*)d_in[2];
    const float* b_ih1 = (const float*)d_in[3];
    const float* b_hh1 = (const float*)d_in[4];
    const float* w_ih2 = (const float*)d_in[5];
    const float* w_hh2 = (const float*)d_in[6];
    const float* b_ih2 = (const float*)d_in[7];
    const float* b_hh2 = (const float*)d_in[8];
    const float* fc1_w = (const float*)d_in[9];
    const float* fc1_b = (const float*)d_in[10];
    const float* fc2_w = (const float*)d_in[11];
    const float* fc2_b = (const float*)d_in[12];
    float* out = (float*)d_out;

    float *xg, *h1, *h2, *tmp;
    cudaGetSymbolAddress((void**)&xg,  g_xg);
    cudaGetSymbolAddress((void**)&h1,  g_h1);
    cudaGetSymbolAddress((void**)&h2,  g_h2);
    cudaGetSymbolAddress((void**)&tmp, g_tmp);

    const int SCAN_SMEM = (64 * 204 + 8 * 820) * (int)sizeof(float); // 78464 B
    cudaFuncSetAttribute(lstm_scan, cudaFuncAttributeMaxDynamicSharedMemorySize, SCAN_SMEM);

    const int MROWS = B_ * T_;          // 153600
    const dim3 grows(13, MROWS / 64);   // N=800 tiles x row tiles
    const dim3 frows(3,  MROWS / 64);   // N=129 tiles

    // 1. x -> [T*B, I]
    transpose_x<<<dim3((T_ + 31) / 32, (I_ + 31) / 32, B_), dim3(32, 8)>>>(x, tmp);
    // 2. xg1 = xt @ w_ih1^T + b_ih1 + b_hh1
    gemm_rm<0><<<grows, 256>>>(tmp, w_ih1, b_ih1, b_hh1, xg, MROWS, I_, G_);
    // 3. layer-1 scan
    lstm_scan<<<100, 256, SCAN_SMEM>>>(xg, w_hh1, h1);
    // 4. xg2 = h1 @ w_ih2^T + b_ih2 + b_hh2   (reuses xg buffer)
    gemm_rm<0><<<grows, 256>>>(h1, w_ih2, b_ih2, b_hh2, xg, MROWS, H_, G_);
    // 5. layer-2 scan
    lstm_scan<<<100, 256, SCAN_SMEM>>>(xg, w_hh2, h2);
    // 6. y1 = relu(h2 @ fc1_w^T + fc1_b)      (reuses tmp buffer)
    gemm_rm<1><<<frows, 256>>>(h2, fc1_w, fc1_b, nullptr, tmp, MROWS, H_, I_);
    // 7. out = sigmoid(y1 @ fc2_w^T + fc2_b), written transposed to [B,129,T]
    gemm_rm<2><<<frows, 256>>>(tmp, fc2_w, fc2_b, nullptr, out, MROWS, I_, I_);
}

// round 3
// speedup vs baseline: 1.0836x; 1.0836x over previous
#include <cuda_runtime.h>
#include <cstdint>
#include <cstdio>

#define B_   256
#define T_   600
#define I_   129
#define H_   200
#define G_   800   // 4*H

// ---------------- scratch (device globals; no cudaMalloc allowed) ----------------
__device__ float g_xg[(size_t)T_ * B_ * G_];    // 491.5 MB (shared by layer1 & layer2)
__device__ float g_h1[(size_t)T_ * B_ * H_];    // 122.9 MB
__device__ float g_h2[(size_t)T_ * B_ * H_];    // 122.9 MB
__device__ float g_tmp[(size_t)T_ * B_ * I_];   // 79.3 MB  (x-transposed, later y1)

// per-batch-group barriers (4 groups of 25 blocks)
__device__ unsigned g_cnt2[4] = {0, 0, 0, 0};
__device__ unsigned g_gen2[4] = {0, 0, 0, 0};

// ---------------- fast activations ----------------
__device__ __forceinline__ float sigmf(float x) {
    return __fdividef(1.f, 1.f + __expf(-x));
}
__device__ __forceinline__ float tanh_fast(float x) {
    float e = __expf(2.f * x);
    return 1.f - __fdividef(2.f, e + 1.f);
}

// ---------------- tf32 helpers ----------------
__device__ __forceinline__ uint32_t f2tf32(float x) {
    uint32_t r;
    asm("cvt.rna.tf32.f32 %0, %1;" : "=r"(r) : "f"(x));
    return r;
}
__device__ __forceinline__ void mma_tf32(float* d, const uint32_t* a, const uint32_t* b) {
    asm volatile(
        "mma.sync.aligned.m16n8k8.row.col.f32.tf32.tf32.f32 "
        "{%0,%1,%2,%3}, {%4,%5,%6,%7}, {%8,%9}, {%0,%1,%2,%3};"
        : "+f"(d[0]), "+f"(d[1]), "+f"(d[2]), "+f"(d[3])
        : "r"(a[0]), "r"(a[1]), "r"(a[2]), "r"(a[3]), "r"(b[0]), "r"(b[1]));
}

// ---------------- transpose x [B,I,T] -> xt [(t*B+b), I] ----------------
__global__ void transpose_x(const float* __restrict__ x, float* __restrict__ xt)
{
    __shared__ float sm[32][33];
    const int b  = blockIdx.z;
    const int i0 = blockIdx.y * 32;
    const int t0 = blockIdx.x * 32;
    const int tx = threadIdx.x, ty = threadIdx.y; // block (32,8)
#pragma unroll
    for (int s = 0; s < 32; s += 8) {
        int i = i0 + ty + s, t = t0 + tx;
        sm[ty + s][tx] = (i < I_ && t < T_) ? x[((size_t)b * I_ + i) * T_ + t] : 0.f;
    }
    __syncthreads();
#pragma unroll
    for (int s = 0; s < 32; s += 8) {
        int t = t0 + ty + s, i = i0 + tx;
        if (t < T_ && i < I_)
            xt[((size_t)t * B_ + b) * I_ + i] = sm[tx][ty + s];
    }
}

// ---------------- tensor-core GEMM (3xTF32 split, ~fp32 accuracy) ----------------
// out = A[M,K] * W[N,K]^T (+bias, activation). Block tile 128(m) x 64(n), Ktile 32.
// 8 warps arranged 4(m) x 2(n); warp tile 32x32 via m16n8k8 fragments.
// MODE 0: out[row*N+n] = v + bias[n] + bias2[n]        (N even -> float2 ok)
// MODE 1: out[row*N+n] = relu(v + bias[n])             (N=129 odd -> scalar stores!)
// MODE 2: out[(b*129+n)*600+t] = sigmoid(v + bias[n]),  t=row>>8, b=row&255
template <int MODE>
__global__ void __launch_bounds__(256) gemm_tc(
    const float* __restrict__ A, const float* __restrict__ W,
    const float* __restrict__ bias, const float* __restrict__ bias2,
    float* __restrict__ out, int M, int K, int N)
{
    extern __shared__ float sm[];
    float* Ah = sm;                 // 128*36
    float* Al = sm + 4608;          // 128*36
    float* Wh = sm + 9216;          // 64*36
    float* Wl = sm + 11520;         // 64*36

    const int tid  = threadIdx.x;
    const int warp = tid >> 5;
    const int lane = tid & 31;
    const int wm   = warp >> 1;     // 0..3
    const int wn   = warp & 1;      // 0..1
    const int g4   = lane >> 2;     // 0..7
    const int tg   = lane & 3;      // 0..3
    const int m0   = blockIdx.y * 128;
    const int n0   = blockIdx.x * 64;

    float acc[2][4][4];
#pragma unroll
    for (int i = 0; i < 2; ++i)
#pragma unroll
        for (int j = 0; j < 4; ++j)
#pragma unroll
            for (int r = 0; r < 4; ++r) acc[i][j][r] = 0.f;

    const int ktiles = (K + 31) >> 5;
    for (int kt = 0; kt < ktiles; ++kt) {
        const int k0 = kt * 32;
        // stage A tile 128x32 (hi/lo), coalesced
#pragma unroll
        for (int i = 0; i < 16; ++i) {
            int lin = tid + 256 * i;          // 0..4095
            int m = lin >> 5, k = lin & 31;
            float v = 0.f;
            if (k0 + k < K) v = A[(size_t)(m0 + m) * K + k0 + k];
            float hi = __uint_as_float(f2tf32(v));
            float lo = v - hi;
            Ah[m * 36 + k] = hi;
            Al[m * 36 + k] = __uint_as_float(f2tf32(lo));
        }
        // stage W tile 64x32 (hi/lo)
#pragma unroll
        for (int i = 0; i < 8; ++i) {
            int lin = tid + 256 * i;          // 0..2047
            int n = lin >> 5, k = lin & 31;
            float v = 0.f;
            if (k0 + k < K && n0 + n < N) v = W[(size_t)(n0 + n) * K + k0 + k];
            float hi = __uint_as_float(f2tf32(v));
            float lo = v - hi;
            Wh[n * 36 + k] = hi;
            Wl[n * 36 + k] = __uint_as_float(f2tf32(lo));
        }
        __syncthreads();

#pragma unroll
        for (int kk = 0; kk < 32; kk += 8) {
            uint32_t ah[2][4], al[2][4];
#pragma unroll
            for (int mf = 0; mf < 2; ++mf) {
                int r = wm * 32 + mf * 16 + g4;
                const float* p = Ah + r * 36 + kk + tg;
                ah[mf][0] = __float_as_uint(p[0]);
                ah[mf][1] = __float_as_uint(p[8 * 36]);
                ah[mf][2] = __float_as_uint(p[4]);
                ah[mf][3] = __float_as_uint(p[8 * 36 + 4]);
                const float* q = Al + r * 36 + kk + tg;
                al[mf][0] = __float_as_uint(q[0]);
                al[mf][1] = __float_as_uint(q[8 * 36]);
                al[mf][2] = __float_as_uint(q[4]);
                al[mf][3] = __float_as_uint(q[8 * 36 + 4]);
            }
            uint32_t bh[4][2], bl[4][2];
#pragma unroll
            for (int nf = 0; nf < 4; ++nf) {
                int c = wn * 32 + nf * 8 + g4;
                const float* p = Wh + c * 36 + kk + tg;
                bh[nf][0] = __float_as_uint(p[0]);
                bh[nf][1] = __float_as_uint(p[4]);
                const float* q = Wl + c * 36 + kk + tg;
                bl[nf][0] = __float_as_uint(q[0]);
                bl[nf][1] = __float_as_uint(q[4]);
            }
#pragma unroll
            for (int mf = 0; mf < 2; ++mf)
#pragma unroll
                for (int nf = 0; nf < 4; ++nf) {
                    mma_tf32(acc[mf][nf], ah[mf], bh[nf]);
                    mma_tf32(acc[mf][nf], ah[mf], bl[nf]);
                    mma_tf32(acc[mf][nf], al[mf], bh[nf]);
                }
        }
        __syncthreads();
    }

    // epilogue
#pragma unroll
    for (int mf = 0; mf < 2; ++mf)
#pragma unroll
        for (int half = 0; half < 2; ++half) {
            int m = m0 + wm * 32 + mf * 16 + g4 + half * 8;
#pragma unroll
            for (int nf = 0; nf < 4; ++nf) {
                int n = n0 + wn * 32 + nf * 8 + tg * 2;
                float v0 = acc[mf][nf][half * 2 + 0];
                float v1 = acc[mf][nf][half * 2 + 1];
                if (MODE == 0) {
                    // N=800 even, n even -> 8B-aligned vector store is safe
                    float2 o;
                    o.x = v0 + bias[n] + bias2[n];
                    o.y = v1 + bias[n + 1] + bias2[n + 1];
                    *(float2*)(out + (size_t)m * N + n) = o;
                } else if (MODE == 1) {
                    // N=129 odd -> scalar stores (alignment!)
                    if (n < N)
                        out[(size_t)m * N + n] = fmaxf(v0 + bias[n], 0.f);
                    if (n + 1 < N)
                        out[(size_t)m * N + n + 1] = fmaxf(v1 + bias[n + 1], 0.f);
                } else {
                    int t = m >> 8, b = m & 255;
                    if (n < N)
                        out[((size_t)b * I_ + n) * T_ + t] = sigmf(v0 + bias[n]);
                    if (n + 1 < N)
                        out[((size_t)b * I_ + n + 1) * T_ + t] = sigmf(v1 + bias[n + 1]);
                }
            }
        }
}

// ---------------- persistent LSTM scan -----------------------------------------
// grid = 100 blocks (4 batch-tiles of 64  x  25 unit-tiles of 8), 256 threads.
// Barrier only within each batch-tile group (25 blocks).
__global__ void __launch_bounds__(256, 1) lstm_scan(
    const float* __restrict__ xg, const float* __restrict__ whh,
    float* __restrict__ hout)
{
    extern __shared__ float sm[];
    float* h_sm = sm;               // 64 * 204 = 13056 floats
    float* w_sm = sm + 64 * 204;    // 8 * 820  = 6560  floats

    const int tid  = threadIdx.x;
    const int bb   = blockIdx.x & 3;
    const int uu   = blockIdx.x >> 2;
    const int b0   = bb * 64;
    const int u_l  = tid & 7;
    const int bgrp = tid >> 3;
    const int u    = uu * 8 + u_l;
    const int b_idx0 = b0 + bgrp * 2;

    // load w_hh slice once: w_sm[u'][k][gate], u-stride 820 (bank-conflict-free)
    for (int idx = tid; idx < 8 * 200 * 4; idx += 256) {
        int g   = idx / 1600;
        int rem = idx - g * 1600;
        int up  = rem / 200;
        int k   = rem - up * 200;
        w_sm[up * 820 + k * 4 + g] = whh[((size_t)(g * H_ + uu * 8 + up)) * H_ + k];
    }

    float c0 = 0.f, c1 = 0.f;

    for (int t = 0; t < T_; ++t) {
        // prefetch x-gate contributions (no h dependency) before the barrier wait
        const float* xr = xg + ((size_t)t * B_ + b_idx0) * G_ + u;
        float xa00 = xr[0],   xa01 = xr[H_],      xa02 = xr[2 * H_],      xa03 = xr[3 * H_];
        float xa10 = xr[G_],  xa11 = xr[G_ + H_], xa12 = xr[G_ + 2 * H_], xa13 = xr[G_ + 3 * H_];

        // group barrier: wait until all 25 blocks of this batch group finished t-1
        if (t > 0) {
            __syncthreads();
            if (tid == 0) {
                unsigned gen = *(volatile unsigned*)&g_gen2[bb];
                __threadfence();
                if (atomicAdd(&g_cnt2[bb], 1u) == 24u) {
                    atomicExch(&g_cnt2[bb], 0u);
                    __threadfence();
                    atomicAdd(&g_gen2[bb], 1u);
                } else {
                    while (*(volatile unsigned*)&g_gen2[bb] == gen) { __nanosleep(32); }
                }
                __threadfence();
            }
            __syncthreads();
        }

        // stage previous h into smem
        if (t == 0) {
            for (int idx = tid; idx < 64 * 204; idx += 256) h_sm[idx] = 0.f;
        } else {
            const float* hp = hout + (size_t)(t - 1) * B_ * H_;
            for (int idx = tid; idx < 64 * 50; idx += 256) {
                int bi = idx / 50;
                int k4 = idx - bi * 50;
                float4 v = *(const float4*)(hp + (size_t)(b0 + bi) * H_ + k4 * 4);
                *(float4*)(h_sm + bi * 204 + k4 * 4) = v;
            }
        }
        __syncthreads();

        // recurrent GEMM: 2 batches x 4 gates, K = 200
        float a00 = 0, a01 = 0, a02 = 0, a03 = 0;
        float a10 = 0, a11 = 0, a12 = 0, a13 = 0;
        const float*  hr0 = h_sm + (bgrp * 2) * 204;
        const float*  hr1 = hr0 + 204;
        const float4* wr  = (const float4*)(w_sm + u_l * 820);
#pragma unroll 8
        for (int k = 0; k < H_; ++k) {
            float4 w4 = wr[k];
            float h0 = hr0[k], h1 = hr1[k];
            a00 += h0 * w4.x; a01 += h0 * w4.y; a02 += h0 * w4.z; a03 += h0 * w4.w;
            a10 += h1 * w4.x; a11 += h1 * w4.y; a12 += h1 * w4.z; a13 += h1 * w4.w;
        }

        // gates + cell update (c stays in registers across all 600 steps)
        float ig = sigmf(a00 + xa00);
        float fg = sigmf(a01 + xa01);
        float gg = tanh_fast(a02 + xa02);
        float og = sigmf(a03 + xa03);
        c0 = fg * c0 + ig * gg;
        float h0o = og * tanh_fast(c0);

        ig = sigmf(a10 + xa10);
        fg = sigmf(a11 + xa11);
        gg = tanh_fast(a12 + xa12);
        og = sigmf(a13 + xa13);
        c1 = fg * c1 + ig * gg;
        float h1o = og * tanh_fast(c1);

        float* ho = hout + ((size_t)t * B_ + b_idx0) * H_ + u;
        ho[0]  = h0o;
        ho[H_] = h1o;

        __threadfence();   // make h(t) visible before arriving at next barrier
        __syncthreads();
    }
}

// ---------------- launch --------------------------------------------------------
extern "C" void kernel_launch(void* const* d_in, const int* in_sizes, int n_in,
                              void* d_out, int out_size)
{
    const float* x     = (const float*)d_in[0];
    const float* w_ih1 = (const float*)d_in[1];
    const float* w_hh1 = (const float*)d_in[2];
    const float* b_ih1 = (const float*)d_in[3];
    const float* b_hh1 = (const float*)d_in[4];
    const float* w_ih2 = (const float*)d_in[5];
    const float* w_hh2 = (const float*)d_in[6];
    const float* b_ih2 = (const float*)d_in[7];
    const float* b_hh2 = (const float*)d_in[8];
    const float* fc1_w = (const float*)d_in[9];
    const float* fc1_b = (const float*)d_in[10];
    const float* fc2_w = (const float*)d_in[11];
    const float* fc2_b = (const float*)d_in[12];
    float* out = (float*)d_out;

    float *xg, *h1, *h2, *tmp;
    cudaGetSymbolAddress((void**)&xg,  g_xg);
    cudaGetSymbolAddress((void**)&h1,  g_h1);
    cudaGetSymbolAddress((void**)&h2,  g_h2);
    cudaGetSymbolAddress((void**)&tmp, g_tmp);

    const int SCAN_SMEM = (64 * 204 + 8 * 820) * (int)sizeof(float); // 78464 B
    cudaFuncSetAttribute(lstm_scan, cudaFuncAttributeMaxDynamicSharedMemorySize, SCAN_SMEM);

    const int GEMM_SMEM = (2 * 128 * 36 + 2 * 64 * 36) * (int)sizeof(float); // 55296 B
    cudaFuncSetAttribute(gemm_tc<0>, cudaFuncAttributeMaxDynamicSharedMemorySize, GEMM_SMEM);
    cudaFuncSetAttribute(gemm_tc<1>, cudaFuncAttributeMaxDynamicSharedMemorySize, GEMM_SMEM);
    cudaFuncSetAttribute(gemm_tc<2>, cudaFuncAttributeMaxDynamicSharedMemorySize, GEMM_SMEM);

    const int MROWS = B_ * T_;                 // 153600
    const dim3 grows(13, MROWS / 128);         // N=800 -> 13 n-tiles
    const dim3 frows(3,  MROWS / 128);         // N=129 -> 3 n-tiles

    // 1. x -> [T*B, I]
    transpose_x<<<dim3((T_ + 31) / 32, (I_ + 31) / 32, B_), dim3(32, 8)>>>(x, tmp);
    // 2. xg1 = xt @ w_ih1^T + b_ih1 + b_hh1
    gemm_tc<0><<<grows, 256, GEMM_SMEM>>>(tmp, w_ih1, b_ih1, b_hh1, xg, MROWS, I_, G_);
    // 3. layer-1 scan
    lstm_scan<<<100, 256, SCAN_SMEM>>>(xg, w_hh1, h1);
    // 4. xg2 = h1 @ w_ih2^T + b_ih2 + b_hh2   (reuses xg buffer)
    gemm_tc<0><<<grows, 256, GEMM_SMEM>>>(h1, w_ih2, b_ih2, b_hh2, xg, MROWS, H_, G_);
    // 5. layer-2 scan
    lstm_scan<<<100, 256, SCAN_SMEM>>>(xg, w_hh2, h2);
    // 6. y1 = relu(h2 @ fc1_w^T + fc1_b)      (reuses tmp buffer)
    gemm_tc<1><<<frows, 256, GEMM_SMEM>>>(h2, fc1_w, fc1_b, nullptr, tmp, MROWS, H_, I_);
    // 7. out = sigmoid(y1 @ fc2_w^T + fc2_b), written transposed to [B,129,T]
    gemm_tc<2><<<frows, 256, GEMM_SMEM>>>(tmp, fc2_w, fc2_b, nullptr, out, MROWS, I_, I_);
}

// round 4
// speedup vs baseline: 1.3323x; 1.2295x over previous
#include <cuda_runtime.h>
#include <cstdint>
#include <cstdio>

#define B_   256
#define T_   600
#define I_   129
#define H_   200
#define G_   800   // 4*H

// ---------------- scratch (device globals; no cudaMalloc allowed) ----------------
__device__ float g_xg[(size_t)T_ * B_ * G_];    // 491.5 MB (shared by layer1 & layer2)
__device__ float g_h1[(size_t)T_ * B_ * H_];    // 122.9 MB
__device__ float g_h2[(size_t)T_ * B_ * H_];    // 122.9 MB
__device__ float g_tmp[(size_t)T_ * B_ * I_];   // 79.3 MB  (x-transposed, later y1)

// per-batch-group barriers (4 groups of 25 blocks)
__device__ unsigned g_cnt2[4] = {0, 0, 0, 0};
__device__ unsigned g_gen2[4] = {0, 0, 0, 0};

// ---------------- fast activations ----------------
__device__ __forceinline__ float sigmf(float x) {
    return __fdividef(1.f, 1.f + __expf(-x));
}
__device__ __forceinline__ float tanh_fast(float x) {
    float e = __expf(2.f * x);
    return 1.f - __fdividef(2.f, e + 1.f);
}

// ---------------- tf32 helpers ----------------
__device__ __forceinline__ uint32_t f2tf32(float x) {
    uint32_t r;
    asm("cvt.rna.tf32.f32 %0, %1;" : "=r"(r) : "f"(x));
    return r;
}
__device__ __forceinline__ void mma_tf32(float* d, const uint32_t* a, const uint32_t* b) {
    asm volatile(
        "mma.sync.aligned.m16n8k8.row.col.f32.tf32.tf32.f32 "
        "{%0,%1,%2,%3}, {%4,%5,%6,%7}, {%8,%9}, {%0,%1,%2,%3};"
        : "+f"(d[0]), "+f"(d[1]), "+f"(d[2]), "+f"(d[3])
        : "r"(a[0]), "r"(a[1]), "r"(a[2]), "r"(a[3]), "r"(b[0]), "r"(b[1]));
}

// ---------------- transpose x [B,I,T] -> xt [(t*B+b), I] ----------------
__global__ void transpose_x(const float* __restrict__ x, float* __restrict__ xt)
{
    __shared__ float sm[32][33];
    const int b  = blockIdx.z;
    const int i0 = blockIdx.y * 32;
    const int t0 = blockIdx.x * 32;
    const int tx = threadIdx.x, ty = threadIdx.y; // block (32,8)
#pragma unroll
    for (int s = 0; s < 32; s += 8) {
        int i = i0 + ty + s, t = t0 + tx;
        sm[ty + s][tx] = (i < I_ && t < T_) ? x[((size_t)b * I_ + i) * T_ + t] : 0.f;
    }
    __syncthreads();
#pragma unroll
    for (int s = 0; s < 32; s += 8) {
        int t = t0 + ty + s, i = i0 + tx;
        if (t < T_ && i < I_)
            xt[((size_t)t * B_ + b) * I_ + i] = sm[tx][ty + s];
    }
}

// ---------------- tensor-core GEMM (3xTF32 split, ~fp32 accuracy) ----------------
template <int MODE>
__global__ void __launch_bounds__(256) gemm_tc(
    const float* __restrict__ A, const float* __restrict__ W,
    const float* __restrict__ bias, const float* __restrict__ bias2,
    float* __restrict__ out, int M, int K, int N)
{
    extern __shared__ float sm[];
    float* Ah = sm;                 // 128*36
    float* Al = sm + 4608;          // 128*36
    float* Wh = sm + 9216;          // 64*36
    float* Wl = sm + 11520;         // 64*36

    const int tid  = threadIdx.x;
    const int warp = tid >> 5;
    const int lane = tid & 31;
    const int wm   = warp >> 1;     // 0..3
    const int wn   = warp & 1;      // 0..1
    const int g4   = lane >> 2;     // 0..7
    const int tg   = lane & 3;      // 0..3
    const int m0   = blockIdx.y * 128;
    const int n0   = blockIdx.x * 64;

    float acc[2][4][4];
#pragma unroll
    for (int i = 0; i < 2; ++i)
#pragma unroll
        for (int j = 0; j < 4; ++j)
#pragma unroll
            for (int r = 0; r < 4; ++r) acc[i][j][r] = 0.f;

    const int ktiles = (K + 31) >> 5;
    for (int kt = 0; kt < ktiles; ++kt) {
        const int k0 = kt * 32;
#pragma unroll
        for (int i = 0; i < 16; ++i) {
            int lin = tid + 256 * i;          // 0..4095
            int m = lin >> 5, k = lin & 31;
            float v = 0.f;
            if (k0 + k < K) v = A[(size_t)(m0 + m) * K + k0 + k];
            float hi = __uint_as_float(f2tf32(v));
            float lo = v - hi;
            Ah[m * 36 + k] = hi;
            Al[m * 36 + k] = __uint_as_float(f2tf32(lo));
        }
#pragma unroll
        for (int i = 0; i < 8; ++i) {
            int lin = tid + 256 * i;          // 0..2047
            int n = lin >> 5, k = lin & 31;
            float v = 0.f;
            if (k0 + k < K && n0 + n < N) v = W[(size_t)(n0 + n) * K + k0 + k];
            float hi = __uint_as_float(f2tf32(v));
            float lo = v - hi;
            Wh[n * 36 + k] = hi;
            Wl[n * 36 + k] = __uint_as_float(f2tf32(lo));
        }
        __syncthreads();

#pragma unroll
        for (int kk = 0; kk < 32; kk += 8) {
            uint32_t ah[2][4], al[2][4];
#pragma unroll
            for (int mf = 0; mf < 2; ++mf) {
                int r = wm * 32 + mf * 16 + g4;
                const float* p = Ah + r * 36 + kk + tg;
                ah[mf][0] = __float_as_uint(p[0]);
                ah[mf][1] = __float_as_uint(p[8 * 36]);
                ah[mf][2] = __float_as_uint(p[4]);
                ah[mf][3] = __float_as_uint(p[8 * 36 + 4]);
                const float* q = Al + r * 36 + kk + tg;
                al[mf][0] = __float_as_uint(q[0]);
                al[mf][1] = __float_as_uint(q[8 * 36]);
                al[mf][2] = __float_as_uint(q[4]);
                al[mf][3] = __float_as_uint(q[8 * 36 + 4]);
            }
            uint32_t bh[4][2], bl[4][2];
#pragma unroll
            for (int nf = 0; nf < 4; ++nf) {
                int c = wn * 32 + nf * 8 + g4;
                const float* p = Wh + c * 36 + kk + tg;
                bh[nf][0] = __float_as_uint(p[0]);
                bh[nf][1] = __float_as_uint(p[4]);
                const float* q = Wl + c * 36 + kk + tg;
                bl[nf][0] = __float_as_uint(q[0]);
                bl[nf][1] = __float_as_uint(q[4]);
            }
#pragma unroll
            for (int mf = 0; mf < 2; ++mf)
#pragma unroll
                for (int nf = 0; nf < 4; ++nf) {
                    mma_tf32(acc[mf][nf], ah[mf], bh[nf]);
                    mma_tf32(acc[mf][nf], ah[mf], bl[nf]);
                    mma_tf32(acc[mf][nf], al[mf], bh[nf]);
                }
        }
        __syncthreads();
    }

#pragma unroll
    for (int mf = 0; mf < 2; ++mf)
#pragma unroll
        for (int half = 0; half < 2; ++half) {
            int m = m0 + wm * 32 + mf * 16 + g4 + half * 8;
#pragma unroll
            for (int nf = 0; nf < 4; ++nf) {
                int n = n0 + wn * 32 + nf * 8 + tg * 2;
                float v0 = acc[mf][nf][half * 2 + 0];
                float v1 = acc[mf][nf][half * 2 + 1];
                if (MODE == 0) {
                    float2 o;
                    o.x = v0 + bias[n] + bias2[n];
                    o.y = v1 + bias[n + 1] + bias2[n + 1];
                    *(float2*)(out + (size_t)m * N + n) = o;
                } else if (MODE == 1) {
                    if (n < N)
                        out[(size_t)m * N + n] = fmaxf(v0 + bias[n], 0.f);
                    if (n + 1 < N)
                        out[(size_t)m * N + n + 1] = fmaxf(v1 + bias[n + 1], 0.f);
                } else {
                    int t = m >> 8, b = m & 255;
                    if (n < N)
                        out[((size_t)b * I_ + n) * T_ + t] = sigmf(v0 + bias[n]);
                    if (n + 1 < N)
                        out[((size_t)b * I_ + n + 1) * T_ + t] = sigmf(v1 + bias[n + 1]);
                }
            }
        }
}

// ---------------- tensor-core persistent LSTM scan ------------------------------
// grid = 100 blocks: 4 batch-groups (64 batches) x 25 unit-blocks (8 units x 4 gates
// = 32 gate-cols). Per step each block computes G[64,32] = h_prev[64,200] @ Whh^T
// slice with 3xTF32 mma.m16n8k8, adds xg, applies activations; c in registers.
//
// smem interleaved layout per (row/col, kb, tg): float4 {hi(k), hi(k+4), lo(k),
// lo(k+4)} with k = kb*8+tg, row stride 400 floats -> every MMA fragment is one
// conflict-free LDS.128. w slice resident for all 600 steps; h re-staged per step.
__global__ void __launch_bounds__(256, 1) lstm_scan_tc(
    const float* __restrict__ xg, const float* __restrict__ whh,
    float* __restrict__ hout)
{
    extern __shared__ float sm[];
    float* w_s = sm;                   // 32 * 400 = 12800
    float* h_s = sm + 12800;           // 64 * 400 = 25600
    float* g_s = sm + 38400;           // 64 * 40  = 2560 (pad 40 -> conflict-free STS.64)

    const int tid  = threadIdx.x;
    const int warp = tid >> 5, lane = tid & 31;
    const int g4   = lane >> 2, tg = lane & 3;
    const int wm   = warp >> 1;        // 0..3 (m-tile)
    const int wn   = warp & 1;         // 0..1 (n-tile)
    const int bb   = blockIdx.x & 3;
    const int uu   = blockIdx.x >> 2;  // 0..24
    const int b0   = bb * 64;
    const int u0   = uu * 8;

    // ---- stage w_hh slice once: col c = gate*8 + unit_local, interleaved hi/lo ----
    for (int i = 0; i < 13; ++i) {
        int lin = tid + 256 * i;                   // 32 cols * 100 slots
        if (lin < 3200) {
            int c   = lin / 100, rem = lin - c * 100;
            int kb  = rem >> 2,  tgs = rem & 3;
            int grow = (c >> 3) * H_ + u0 + (c & 7);   // gate*200 + unit
            int k0  = kb * 8 + tgs;
            float w0 = whh[(size_t)grow * H_ + k0];
            float w1 = whh[(size_t)grow * H_ + k0 + 4];
            float h0 = __uint_as_float(f2tf32(w0));
            float h1 = __uint_as_float(f2tf32(w1));
            float4 v = make_float4(h0, h1,
                                   __uint_as_float(f2tf32(w0 - h0)),
                                   __uint_as_float(f2tf32(w1 - h1)));
            *(float4*)(w_s + c * 400 + kb * 16 + tgs * 4) = v;
        }
    }

    // epilogue ownership: thread handles (b, ul) and (b, ul+1)
    const int eb  = tid >> 2;          // 0..63
    const int eul = (tid & 3) * 2;     // 0,2,4,6
    float c0 = 0.f, c1 = 0.f;

    // fragment base pointers
    const float* hA = h_s + (wm * 16 + g4) * 400 + tg * 4;
    const float* hB = hA + 8 * 400;
    const float* wA = w_s + (wn * 16 + g4) * 400 + tg * 4;
    const float* wB = wA + 8 * 400;

    for (int t = 0; t < T_; ++t) {
        // prefetch xg for this step's epilogue (no h dependency)
        const float* xr = xg + ((size_t)t * B_ + b0 + eb) * G_ + u0 + eul;
        float xa00 = xr[0],      xa01 = xr[H_],      xa02 = xr[2 * H_],      xa03 = xr[3 * H_];
        float xa10 = xr[1],      xa11 = xr[H_ + 1],  xa12 = xr[2 * H_ + 1],  xa13 = xr[3 * H_ + 1];

        // group barrier (25 blocks): h(t-1) of all units visible before staging
        if (t > 0) {
            __syncthreads();
            if (tid == 0) {
                unsigned gen = *(volatile unsigned*)&g_gen2[bb];
                if (atomicAdd(&g_cnt2[bb], 1u) == 24u) {
                    atomicExch(&g_cnt2[bb], 0u);
                    __threadfence();
                    atomicAdd(&g_gen2[bb], 1u);
                } else {
                    while (*(volatile unsigned*)&g_gen2[bb] == gen) { __nanosleep(32); }
                }
                __threadfence();
            }
            __syncthreads();
        }

        // ---- stage h(t-1): 64x200 fp32 -> interleaved hi/lo smem ----
        if (t == 0) {
            float4 z = make_float4(0.f, 0.f, 0.f, 0.f);
#pragma unroll
            for (int i = 0; i < 25; ++i) {
                int lin = tid + 256 * i;               // 6400 slots
                *(float4*)(h_s + (lin / 100) * 400 + (lin % 100) * 4) = z;
            }
        } else {
            const float* hp = hout + (size_t)(t - 1) * B_ * H_;
#pragma unroll
            for (int i = 0; i < 25; ++i) {
                int lin = tid + 256 * i;
                int row = lin / 100, rem = lin - row * 100;
                int kb = rem >> 2, tgs = rem & 3;
                int k0 = kb * 8 + tgs;
                const float* src = hp + (size_t)(b0 + row) * H_;
                float v0 = __ldcg(src + k0);
                float v1 = __ldcg(src + k0 + 4);
                float h0 = __uint_as_float(f2tf32(v0));
                float h1 = __uint_as_float(f2tf32(v1));
                float4 v = make_float4(h0, h1,
                                       __uint_as_float(f2tf32(v0 - h0)),
                                       __uint_as_float(f2tf32(v1 - h1)));
                *(float4*)(h_s + row * 400 + kb * 16 + tgs * 4) = v;
            }
        }
        __syncthreads();

        // ---- MMA: G[64,32] = h @ w^T (3xTF32) ----
        float acc0[4] = {0.f, 0.f, 0.f, 0.f};
        float acc1[4] = {0.f, 0.f, 0.f, 0.f};
#pragma unroll 5
        for (int kb = 0; kb < 25; ++kb) {
            float4 A0 = *(const float4*)(hA + kb * 16);
            float4 A1 = *(const float4*)(hB + kb * 16);
            float4 B0 = *(const float4*)(wA + kb * 16);
            float4 B1 = *(const float4*)(wB + kb * 16);
            uint32_t ah[4] = {__float_as_uint(A0.x), __float_as_uint(A1.x),
                              __float_as_uint(A0.y), __float_as_uint(A1.y)};
            uint32_t al[4] = {__float_as_uint(A0.z), __float_as_uint(A1.z),
                              __float_as_uint(A0.w), __float_as_uint(A1.w)};
            uint32_t bh0[2] = {__float_as_uint(B0.x), __float_as_uint(B0.y)};
            uint32_t bl0[2] = {__float_as_uint(B0.z), __float_as_uint(B0.w)};
            uint32_t bh1[2] = {__float_as_uint(B1.x), __float_as_uint(B1.y)};
            uint32_t bl1[2] = {__float_as_uint(B1.z), __float_as_uint(B1.w)};
            mma_tf32(acc0, ah, bh0);
            mma_tf32(acc0, ah, bl0);
            mma_tf32(acc0, al, bh0);
            mma_tf32(acc1, ah, bh1);
            mma_tf32(acc1, ah, bl1);
            mma_tf32(acc1, al, bh1);
        }

        // ---- accumulators -> g_s (padded stride 40) ----
        {
            float* d0 = g_s + (wm * 16 + g4) * 40 + wn * 16 + tg * 2;
            *(float2*)(d0)           = make_float2(acc0[0], acc0[1]);
            *(float2*)(d0 + 8)       = make_float2(acc1[0], acc1[1]);
            *(float2*)(d0 + 8 * 40)     = make_float2(acc0[2], acc0[3]);
            *(float2*)(d0 + 8 * 40 + 8) = make_float2(acc1[2], acc1[3]);
        }
        __syncthreads();

        // ---- gates + cell update for 2 (b,ul) pairs ----
        {
            const float* gr = g_s + eb * 40 + eul;
            float i0v = gr[0]  + xa00, f0v = gr[8]  + xa01;
            float g0v = gr[16] + xa02, o0v = gr[24] + xa03;
            float i1v = gr[1]  + xa10, f1v = gr[9]  + xa11;
            float g1v = gr[17] + xa12, o1v = gr[25] + xa13;

            float ig = sigmf(i0v), fg = sigmf(f0v);
            float gg = tanh_fast(g0v), og = sigmf(o0v);
            c0 = fg * c0 + ig * gg;
            float h0o = og * tanh_fast(c0);

            ig = sigmf(i1v); fg = sigmf(f1v);
            gg = tanh_fast(g1v); og = sigmf(o1v);
            c1 = fg * c1 + ig * gg;
            float h1o = og * tanh_fast(c1);

            float* ho = hout + ((size_t)t * B_ + b0 + eb) * H_ + u0 + eul;
            __stcg(ho, h0o);
            __stcg(ho + 1, h1o);
        }
        __threadfence();   // order h stores before next barrier arrive
    }
}

// ---------------- launch --------------------------------------------------------
extern "C" void kernel_launch(void* const* d_in, const int* in_sizes, int n_in,
                              void* d_out, int out_size)
{
    const float* x     = (const float*)d_in[0];
    const float* w_ih1 = (const float*)d_in[1];
    const float* w_hh1 = (const float*)d_in[2];
    const float* b_ih1 = (const float*)d_in[3];
    const float* b_hh1 = (const float*)d_in[4];
    const float* w_ih2 = (const float*)d_in[5];
    const float* w_hh2 = (const float*)d_in[6];
    const float* b_ih2 = (const float*)d_in[7];
    const float* b_hh2 = (const float*)d_in[8];
    const float* fc1_w = (const float*)d_in[9];
    const float* fc1_b = (const float*)d_in[10];
    const float* fc2_w = (const float*)d_in[11];
    const float* fc2_b = (const float*)d_in[12];
    float* out = (float*)d_out;

    float *xg, *h1, *h2, *tmp;
    cudaGetSymbolAddress((void**)&xg,  g_xg);
    cudaGetSymbolAddress((void**)&h1,  g_h1);
    cudaGetSymbolAddress((void**)&h2,  g_h2);
    cudaGetSymbolAddress((void**)&tmp, g_tmp);

    const int SCAN_SMEM = (12800 + 25600 + 2560) * (int)sizeof(float); // 163840 B
    cudaFuncSetAttribute(lstm_scan_tc, cudaFuncAttributeMaxDynamicSharedMemorySize, SCAN_SMEM);

    const int GEMM_SMEM = (2 * 128 * 36 + 2 * 64 * 36) * (int)sizeof(float); // 55296 B
    cudaFuncSetAttribute(gemm_tc<0>, cudaFuncAttributeMaxDynamicSharedMemorySize, GEMM_SMEM);
    cudaFuncSetAttribute(gemm_tc<1>, cudaFuncAttributeMaxDynamicSharedMemorySize, GEMM_SMEM);
    cudaFuncSetAttribute(gemm_tc<2>, cudaFuncAttributeMaxDynamicSharedMemorySize, GEMM_SMEM);

    const int MROWS = B_ * T_;                 // 153600
    const dim3 grows(13, MROWS / 128);         // N=800 -> 13 n-tiles
    const dim3 frows(3,  MROWS / 128);         // N=129 -> 3 n-tiles

    // 1. x -> [T*B, I]
    transpose_x<<<dim3((T_ + 31) / 32, (I_ + 31) / 32, B_), dim3(32, 8)>>>(x, tmp);
    // 2. xg1 = xt @ w_ih1^T + b_ih1 + b_hh1
    gemm_tc<0><<<grows, 256, GEMM_SMEM>>>(tmp, w_ih1, b_ih1, b_hh1, xg, MROWS, I_, G_);
    // 3. layer-1 scan (tensor cores)
    lstm_scan_tc<<<100, 256, SCAN_SMEM>>>(xg, w_hh1, h1);
    // 4. xg2 = h1 @ w_ih2^T + b_ih2 + b_hh2
    gemm_tc<0><<<grows, 256, GEMM_SMEM>>>(h1, w_ih2, b_ih2, b_hh2, xg, MROWS, H_, G_);
    // 5. layer-2 scan
    lstm_scan_tc<<<100, 256, SCAN_SMEM>>>(xg, w_hh2, h2);
    // 6. y1 = relu(h2 @ fc1_w^T + fc1_b)
    gemm_tc<1><<<frows, 256, GEMM_SMEM>>>(h2, fc1_w, fc1_b, nullptr, tmp, MROWS, H_, I_);
    // 7. out = sigmoid(y1 @ fc2_w^T + fc2_b), transposed store to [B,129,T]
    gemm_tc<2><<<frows, 256, GEMM_SMEM>>>(tmp, fc2_w, fc2_b, nullptr, out, MROWS, I_, I_);
}